// round 3
// baseline (speedup 1.0000x reference)
#include <cuda_runtime.h>
#include <cuda_bf16.h>

// Problem constants (fixed by the reference setup)
constexpr int B        = 16;
constexpr int H        = 16;
constexpr int D        = 128;
constexpr int BS       = 16;    // tokens per physical KV block
constexpr int BPS      = 128;   // blocks per sequence
constexpr int NSPLIT   = 8;
constexpr int CHUNK    = 256;   // tokens per split (NSPLIT*CHUNK = 2048)
constexpr int NW       = 8;     // warps per CTA
constexpr int THREADS  = NW * 32;

// Scratch for split-KV partials (no cudaMalloc allowed)
__device__ float g_part_acc[B * H * NSPLIT * D];   // 1 MB
__device__ float g_part_ml [B * H * NSPLIT * 2];   // (m, l) per partial

__device__ __forceinline__ float warp_sum(float v) {
    v += __shfl_xor_sync(0xffffffffu, v, 16);
    v += __shfl_xor_sync(0xffffffffu, v, 8);
    v += __shfl_xor_sync(0xffffffffu, v, 4);
    v += __shfl_xor_sync(0xffffffffu, v, 2);
    v += __shfl_xor_sync(0xffffffffu, v, 1);
    return v;
}
__device__ __forceinline__ float warp_max(float v) {
    v = fmaxf(v, __shfl_xor_sync(0xffffffffu, v, 16));
    v = fmaxf(v, __shfl_xor_sync(0xffffffffu, v, 8));
    v = fmaxf(v, __shfl_xor_sync(0xffffffffu, v, 4));
    v = fmaxf(v, __shfl_xor_sync(0xffffffffu, v, 2));
    v = fmaxf(v, __shfl_xor_sync(0xffffffffu, v, 1));
    return v;
}

// ---------------------------------------------------------------------------
// Kernel 1: per-(b,h,split) partial attention.
// Pass 1: scores into SMEM (warp per token, lane per 4 dims, coalesced 512B).
// Block softmax (local max m, weights p, local sum l).
// Pass 2: acc[d] = sum_t p_t * V[t][d], combined across warps in SMEM.
// Writes (m, l, acc[128]) to global scratch.
// ---------------------------------------------------------------------------
__global__ __launch_bounds__(THREADS)
void pa_split_kernel(const float* __restrict__ q,
                     const float* __restrict__ kc,
                     const float* __restrict__ vc,
                     const int*   __restrict__ bt,
                     const int*   __restrict__ cl)
{
    __shared__ float  sc[CHUNK];
    __shared__ float4 wacc4[NW][D / 4];
    __shared__ int    sblk[CHUNK / BS];
    __shared__ float  red[NW];
    __shared__ float  s_m, s_l;

    const int tid  = threadIdx.x;
    const int lane = tid & 31;
    const int wid  = tid >> 5;

    const int s  = blockIdx.x & (NSPLIT - 1);
    const int bh = blockIdx.x >> 3;          // b*H + h
    const int b  = bh >> 4;
    const int h  = bh & 15;

    const int ctx   = cl[b];
    const int t0    = s * CHUNK;
    const int pbase = bh * NSPLIT + s;

    int n = ctx - t0;
    if (n > CHUNK) n = CHUNK;

    if (n <= 0) {
        // Inactive split: deterministic zero partial.
        if (tid < D) g_part_acc[pbase * D + tid] = 0.0f;
        if (tid == 0) {
            g_part_ml[2 * pbase + 0] = -3.0e38f;
            g_part_ml[2 * pbase + 1] = 0.0f;
        }
        return;
    }

    if (tid < CHUNK / BS)
        sblk[tid] = bt[b * BPS + s * (CHUNK / BS) + tid];

    const float4 q4 = reinterpret_cast<const float4*>(q + (size_t)bh * D)[lane];
    __syncthreads();

    const float scale = 0.08838834764831845f;   // 1/sqrt(128)

    // ---- Pass 1: scores ---------------------------------------------------
    for (int t = wid; t < n; t += 2 * NW) {
        const int t2   = t + NW;
        const bool has2 = (t2 < n);

        const float* kp1 = kc + ((((size_t)sblk[t >> 4] * BS + (t & 15)) * H + h) * D);
        float4 k1 = reinterpret_cast<const float4*>(kp1)[lane];

        float4 k2 = make_float4(0.f, 0.f, 0.f, 0.f);
        if (has2) {
            const float* kp2 = kc + ((((size_t)sblk[t2 >> 4] * BS + (t2 & 15)) * H + h) * D);
            k2 = reinterpret_cast<const float4*>(kp2)[lane];
        }

        float d1 = k1.x * q4.x + k1.y * q4.y + k1.z * q4.z + k1.w * q4.w;
        float d2 = k2.x * q4.x + k2.y * q4.y + k2.z * q4.z + k2.w * q4.w;

        d1 = warp_sum(d1);
        if (has2) d2 = warp_sum(d2);

        if (lane == 0) {
            sc[t] = d1 * scale;
            if (has2) sc[t2] = d2 * scale;
        }
    }
    __syncthreads();

    // ---- Block softmax over the chunk --------------------------------------
    float v = (tid < n) ? sc[tid] : -3.0e38f;
    float m = warp_max(v);
    if (lane == 0) red[wid] = m;
    __syncthreads();
    if (wid == 0) {
        float x = (lane < NW) ? red[lane] : -3.0e38f;
        x = warp_max(x);
        if (lane == 0) s_m = x;
    }
    __syncthreads();
    const float M = s_m;

    float p = (tid < n) ? __expf(v - M) : 0.0f;
    if (tid < n) sc[tid] = p;

    float l = warp_sum(p);
    if (lane == 0) red[wid] = l;
    __syncthreads();
    if (wid == 0) {
        float x = (lane < NW) ? red[lane] : 0.0f;
        x = warp_sum(x);
        if (lane == 0) s_l = x;
    }
    __syncthreads();

    // ---- Pass 2: weighted V accumulation ------------------------------------
    float4 acc = make_float4(0.f, 0.f, 0.f, 0.f);
    #pragma unroll 2
    for (int t = wid; t < n; t += NW) {
        const float pt = sc[t];
        const float* vp = vc + ((((size_t)sblk[t >> 4] * BS + (t & 15)) * H + h) * D);
        const float4 v4 = reinterpret_cast<const float4*>(vp)[lane];
        acc.x += pt * v4.x;
        acc.y += pt * v4.y;
        acc.z += pt * v4.z;
        acc.w += pt * v4.w;
    }
    wacc4[wid][lane] = acc;
    __syncthreads();

    if (tid < D) {
        const float* wf = reinterpret_cast<const float*>(wacc4);
        float o = 0.0f;
        #pragma unroll
        for (int w = 0; w < NW; ++w) o += wf[w * D + tid];
        g_part_acc[pbase * D + tid] = o;
    }
    if (tid == 0) {
        g_part_ml[2 * pbase + 0] = M;
        g_part_ml[2 * pbase + 1] = s_l;
    }
}

// ---------------------------------------------------------------------------
// Kernel 2: combine NSPLIT partials per (b,h) via log-sum-exp.
// ---------------------------------------------------------------------------
__global__ __launch_bounds__(D)
void pa_combine_kernel(float* __restrict__ out)
{
    const int bh = blockIdx.x;
    const int d  = threadIdx.x;

    float lm[NSPLIT], ll[NSPLIT];
    float M = -3.4e38f;
    #pragma unroll
    for (int s = 0; s < NSPLIT; ++s) {
        lm[s] = g_part_ml[2 * (bh * NSPLIT + s) + 0];
        ll[s] = g_part_ml[2 * (bh * NSPLIT + s) + 1];
        M = fmaxf(M, lm[s]);
    }

    float L = 0.0f, o = 0.0f;
    #pragma unroll
    for (int s = 0; s < NSPLIT; ++s) {
        const float f = __expf(lm[s] - M);
        L += ll[s] * f;
        o += g_part_acc[(bh * NSPLIT + s) * D + d] * f;
    }
    out[bh * D + d] = o / L;
}

extern "C" void kernel_launch(void* const* d_in, const int* in_sizes, int n_in,
                              void* d_out, int out_size)
{
    const float* q  = (const float*)d_in[0];
    const float* kc = (const float*)d_in[1];
    const float* vc = (const float*)d_in[2];
    const int*   bt = (const int*)d_in[3];
    const int*   cl = (const int*)d_in[4];
    float* out = (float*)d_out;

    pa_split_kernel<<<B * H * NSPLIT, THREADS>>>(q, kc, vc, bt, cl);
    pa_combine_kernel<<<B * H, D>>>(out);
}